// round 3
// baseline (speedup 1.0000x reference)
#include <cuda_runtime.h>
#include <cstdint>

// Problem dims (fixed by dataset)
#define NQ1   10001
#define NQA1  20001
#define MSZ   64
#define KD    128
#define VD    256
#define VM    256
#define FD    128
#define BB    512
#define SS    512

typedef unsigned long long ull;

// ---------------------------------------------------------------------------
// f32x2 packed-math helpers
// ---------------------------------------------------------------------------
__device__ __forceinline__ ull pk2(float a, float b) {
    ull r; asm("mov.b64 %0, {%1, %2};" : "=l"(r) : "f"(a), "f"(b)); return r;
}
__device__ __forceinline__ void upk2(ull p, float& a, float& b) {
    asm("mov.b64 {%0, %1}, %2;" : "=f"(a), "=f"(b) : "l"(p));
}
__device__ __forceinline__ ull fma2(ull a, ull b, ull c) {
    ull d; asm("fma.rn.f32x2 %0, %1, %2, %3;" : "=l"(d) : "l"(a), "l"(b), "l"(c)); return d;
}
__device__ __forceinline__ ull add2(ull a, ull b) {
    ull d; asm("add.rn.f32x2 %0, %1, %2;" : "=l"(d) : "l"(a), "l"(b)); return d;
}

// ---------------------------------------------------------------------------
// Scratch tables
// ---------------------------------------------------------------------------
__device__ float g_wtab [NQ1  * MSZ];
__device__ float g_fktab[NQ1  * FD ];
__device__ float g_etab [NQA1 * VM ];
__device__ float g_atab [NQA1 * VM ];
__device__ float g_WeT  [VD * VM];
__device__ float g_WaT  [VD * VM];

// ---------------------------------------------------------------------------
// Transpose We/Wa (256x256) into [j][u] layout
// ---------------------------------------------------------------------------
__global__ void transpose_we_wa(const float* __restrict__ We,
                                const float* __restrict__ Wa)
{
    __shared__ float tile[32][33];
    const float* src = blockIdx.z ? Wa : We;
    float* dst = blockIdx.z ? g_WaT : g_WeT;
    const int bx = blockIdx.x * 32;
    const int by = blockIdx.y * 32;
    #pragma unroll
    for (int k = 0; k < 4; k++)
        tile[threadIdx.y + k * 8][threadIdx.x] =
            src[(by + threadIdx.y + k * 8) * VD + bx + threadIdx.x];
    __syncthreads();
    #pragma unroll
    for (int k = 0; k < 4; k++)
        dst[(bx + threadIdx.y + k * 8) * VM + by + threadIdx.x] =
            tile[threadIdx.x][threadIdx.y + k * 8];
}

// ---------------------------------------------------------------------------
// Kernel A: per-q tables (32 indices/block, coalesced + conflict-free)
// ---------------------------------------------------------------------------
#define WTI 32
#define WFK_SMEM ((WTI*KD + MSZ*132 + FD*132 + WTI*MSZ) * 4)

__global__ void __launch_bounds__(256)
build_wfk_kernel(const float* __restrict__ k_emb, const float* __restrict__ Mk,
                 const float* __restrict__ Wf,    const float* __restrict__ bf)
{
    extern __shared__ float sm[];
    float* k_s   = sm;
    float* Mk_s  = sm + WTI * KD;
    float* Wfk_s = Mk_s + MSZ * 132;
    float* sc_s  = Wfk_s + FD * 132;

    const int tid  = threadIdx.x;
    const int base = blockIdx.x * WTI;

    for (int idx = tid; idx < WTI * KD; idx += 256) {
        const int i = idx >> 7, j = idx & 127;
        const int gi = min(base + i, NQ1 - 1);
        k_s[i * KD + j] = k_emb[gi * KD + j];
    }
    for (int idx = tid; idx < MSZ * KD; idx += 256) {
        const int m = idx >> 7, j = idx & 127;
        Mk_s[m * 132 + j] = Mk[idx];
    }
    for (int idx = tid; idx < FD * KD; idx += 256) {
        const int ff = idx >> 7, j = idx & 127;
        Wfk_s[ff * 132 + j] = Wf[ff * (KD + VM) + VM + j];
    }
    __syncthreads();

    {
        const int m = tid & 63, ig = tid >> 6;
        float acc[8];
        #pragma unroll
        for (int ii = 0; ii < 8; ii++) acc[ii] = 0.f;
        #pragma unroll 4
        for (int j4 = 0; j4 < KD / 4; j4++) {
            const float4 mk = *reinterpret_cast<const float4*>(Mk_s + m * 132 + j4 * 4);
            #pragma unroll
            for (int ii = 0; ii < 8; ii++) {
                const float4 kv = *reinterpret_cast<const float4*>(k_s + (ig * 8 + ii) * KD + j4 * 4);
                acc[ii] = fmaf(mk.x, kv.x, fmaf(mk.y, kv.y, fmaf(mk.z, kv.z, fmaf(mk.w, kv.w, acc[ii]))));
            }
        }
        #pragma unroll
        for (int ii = 0; ii < 8; ii++) sc_s[(ig * 8 + ii) * MSZ + m] = acc[ii];
    }
    __syncthreads();

    {
        const int lane = tid & 31, w = tid >> 5;
        #pragma unroll
        for (int rep = 0; rep < 4; rep++) {
            const int i = w + rep * 8;
            const float sa = sc_s[i * MSZ + lane];
            const float sb = sc_s[i * MSZ + 32 + lane];
            float mx = fmaxf(sa, sb);
            #pragma unroll
            for (int o = 16; o > 0; o >>= 1) mx = fmaxf(mx, __shfl_xor_sync(0xffffffffu, mx, o));
            const float ea = expf(sa - mx), eb = expf(sb - mx);
            float s = ea + eb;
            #pragma unroll
            for (int o = 16; o > 0; o >>= 1) s += __shfl_xor_sync(0xffffffffu, s, o);
            const float inv = 1.f / s;
            const int gi = base + i;
            if (gi < NQ1) {
                g_wtab[gi * MSZ + lane]      = ea * inv;
                g_wtab[gi * MSZ + 32 + lane] = eb * inv;
            }
        }
    }

    {
        const int ff = tid & 127, h = tid >> 7;
        float fa[16];
        #pragma unroll
        for (int ii = 0; ii < 16; ii++) fa[ii] = 0.f;
        #pragma unroll 2
        for (int j4 = 0; j4 < KD / 4; j4++) {
            const float4 wv = *reinterpret_cast<const float4*>(Wfk_s + ff * 132 + j4 * 4);
            #pragma unroll
            for (int ii = 0; ii < 16; ii++) {
                const float4 kv = *reinterpret_cast<const float4*>(k_s + (h * 16 + ii) * KD + j4 * 4);
                fa[ii] = fmaf(wv.x, kv.x, fmaf(wv.y, kv.y, fmaf(wv.z, kv.z, fmaf(wv.w, kv.w, fa[ii]))));
            }
        }
        const float bff = bf[ff];
        #pragma unroll
        for (int ii = 0; ii < 16; ii++) {
            const int gi = base + h * 16 + ii;
            if (gi < NQ1) g_fktab[gi * FD + ff] = fa[ii] + bff;
        }
    }
}

// ---------------------------------------------------------------------------
// Kernel B: per-qa tables from transposed weights
// ---------------------------------------------------------------------------
#define TI 32
__global__ void __launch_bounds__(256)
build_ea_kernel(const float* __restrict__ v_emb,
                const float* __restrict__ be, const float* __restrict__ ba)
{
    __shared__ float4 v_s[TI * (VD / 4)];
    const int tid  = threadIdx.x;
    const int base = blockIdx.x * TI;

    for (int idx = tid; idx < TI * (VD / 4); idx += 256) {
        const int i = idx >> 6, j4 = idx & 63;
        const int gi = min(base + i, NQA1 - 1);
        v_s[i * (VD / 4) + j4] = reinterpret_cast<const float4*>(v_emb)[gi * (VD / 4) + j4];
    }
    __syncthreads();

    const int u = tid;
    float acce[TI], acca[TI];
    #pragma unroll
    for (int i = 0; i < TI; i++) { acce[i] = 0.f; acca[i] = 0.f; }

    #pragma unroll 1
    for (int j4 = 0; j4 < VD / 4; j4++) {
        const int j = j4 * 4;
        const float we0 = g_WeT[(j + 0) * VM + u];
        const float we1 = g_WeT[(j + 1) * VM + u];
        const float we2 = g_WeT[(j + 2) * VM + u];
        const float we3 = g_WeT[(j + 3) * VM + u];
        const float wa0 = g_WaT[(j + 0) * VM + u];
        const float wa1 = g_WaT[(j + 1) * VM + u];
        const float wa2 = g_WaT[(j + 2) * VM + u];
        const float wa3 = g_WaT[(j + 3) * VM + u];
        #pragma unroll
        for (int i = 0; i < TI; i++) {
            const float4 v = v_s[i * (VD / 4) + j4];
            acce[i] = fmaf(we0, v.x, fmaf(we1, v.y, fmaf(we2, v.z, fmaf(we3, v.w, acce[i]))));
            acca[i] = fmaf(wa0, v.x, fmaf(wa1, v.y, fmaf(wa2, v.z, fmaf(wa3, v.w, acca[i]))));
        }
    }

    const float bei = be[u], bai = ba[u];
    #pragma unroll
    for (int i = 0; i < TI; i++) {
        const int gi = base + i;
        if (gi < NQA1) {
            g_etab[gi * VM + u] = 1.f / (1.f + expf(-(acce[i] + bei)));
            g_atab[gi * VM + u] = tanhf(acca[i] + bai);
        }
    }
}

__global__ void init_out_kernel(float* __restrict__ out, const float* __restrict__ bp)
{
    const int i = blockIdx.x * 256 + threadIdx.x;
    if (i < BB * SS) out[i] = bp[0];
}

// ---------------------------------------------------------------------------
// Main kernel: 512 threads/CTA (16 warps), software-pipelined, 1 barrier/step
//   Phase A role: u = tid&255, mh = tid>>8   -> Mv[mh*32..+32, u] in 16 packed
//   Phase B role: f = tid&127, g  = tid>>7   -> Wf[f, g*64..+64]  in 32 packed
//   Pipeline at iter i:  A(i) | r-fold(i-1) | B(i-2) | E(i-3) | prefetch(i+1)
// ---------------------------------------------------------------------------
#define STG 258   // padded stage row stride (floats): 2-way max conflicts

__global__ void __launch_bounds__(512, 1)
dkvmn_main_kernel(const int* __restrict__ q,  const int* __restrict__ qa,
                  const float* __restrict__ Wf, const float* __restrict__ Wp,
                  const float* __restrict__ Mv0, float* __restrict__ out)
{
    __shared__ __align__(16) float s_w [2][MSZ];
    __shared__ __align__(16) float s_rp[2][512];
    __shared__ __align__(16) float s_r [2][VM];
    __shared__ __align__(16) float s_fp[2][512];
    __shared__ int s_q[SS], s_qa[SS];
    __shared__ __align__(16) float s_stage[32 * STG];   // 33 KB (total 47.7 KB)

    const int b   = blockIdx.x;
    const int tid = threadIdx.x;
    const int u   = tid & 255;
    const int mh  = tid >> 8;       // 0/1 : m-half for phase A
    const int f   = tid & 127;
    const int g   = tid >> 7;       // 0..3 : j-quarter for phase B

    for (int idx = tid; idx < SS; idx += 512) {
        s_q [idx] = q [b * SS + idx];
        s_qa[idx] = qa[b * SS + idx];
    }

    // ---- Wf_r -> registers via coalesced smem bounce (4 chunks of 32 rows)
    ull wfr[32];
    #pragma unroll 1
    for (int c = 0; c < 4; c++) {
        if (c) __syncthreads();
        for (int idx = tid; idx < 32 * VM; idx += 512) {
            const int fr = idx >> 8, uu = idx & 255;
            s_stage[fr * STG + uu] = Wf[(c * 32 + fr) * (KD + VM) + uu];
        }
        __syncthreads();
        if ((f >> 5) == c) {
            const ull* p = reinterpret_cast<const ull*>(s_stage + (f & 31) * STG + g * 64);
            #pragma unroll
            for (int j2 = 0; j2 < 32; j2++) wfr[j2] = p[j2];
        }
    }

    // ---- state: Mv[mh-half, u] as 16 packed pairs -------------------------
    ull mv2[16];
    #pragma unroll
    for (int m2 = 0; m2 < 16; m2++) {
        const int m = mh * 32 + 2 * m2;
        mv2[m2] = pk2(Mv0[m * VM + u], Mv0[(m + 1) * VM + u]);
    }

    const float wp_f = Wp[f];

    // ---- init pipeline: w(0), e/a(0) --------------------------------------
    float e_c, a_c, fk_c = 0.f;
    {
        const int q0 = s_q[0], qa0 = s_qa[0];
        e_c = g_etab[qa0 * VM + u];
        a_c = g_atab[qa0 * VM + u];
        if (tid < MSZ) s_w[0][tid] = g_wtab[q0 * MSZ + tid];
    }
    __syncthreads();

    #pragma unroll 1
    for (int i = 0; i < SS + 3; i++) {
        const int buf = i & 1;

        // ---- P(i+1): issue prefetch LDGs early ---------------------------
        const int tn  = (i + 1 < SS) ? i + 1 : SS - 1;
        const int qn  = s_q[tn], qan = s_qa[tn];
        const float e_pf = g_etab[qan * VM + u];
        const float a_pf = g_atab[qan * VM + u];
        float w_pf = 0.f, fk_pf = 0.f;
        if (tid < MSZ) w_pf = g_wtab[qn * MSZ + tid];
        if (tid < FD) {
            int tf = i - 2; tf = (tf < 0) ? 0 : ((tf < SS) ? tf : SS - 1);
            fk_pf = g_fktab[s_q[tf] * FD + f];
        }

        // ---- A(i): r partials + Mv update (f32x2) ------------------------
        if (i < SS) {
            const ull ne2 = pk2(-e_c, -e_c);
            const ull a2  = pk2(a_c, a_c);
            ull r0 = 0ull, r1 = 0ull, r2 = 0ull, r3 = 0ull;
            const ulonglong2* sw2 =
                reinterpret_cast<const ulonglong2*>(&s_w[buf][mh * 32]);
            #pragma unroll
            for (int m4 = 0; m4 < 8; m4++) {
                const ulonglong2 wp = sw2[m4];
                const ull mA = mv2[2 * m4], mB = mv2[2 * m4 + 1];
                if (m4 & 1) { r2 = fma2(wp.x, mA, r2); r3 = fma2(wp.y, mB, r3); }
                else        { r0 = fma2(wp.x, mA, r0); r1 = fma2(wp.y, mB, r1); }
                const ull tA = fma2(ne2, mA, a2);
                const ull tB = fma2(ne2, mB, a2);
                mv2[2 * m4]     = fma2(wp.x, tA, mA);
                mv2[2 * m4 + 1] = fma2(wp.y, tB, mB);
            }
            float x0, x1, x2, x3, x4, x5, x6, x7;
            upk2(r0, x0, x1); upk2(r1, x2, x3);
            upk2(r2, x4, x5); upk2(r3, x6, x7);
            s_rp[buf][mh * 256 + u] = ((x0 + x1) + (x2 + x3)) + ((x4 + x5) + (x6 + x7));
        }

        // ---- R(i-1): fold the two m-halves into s_r ----------------------
        if (i >= 1 && i <= SS && tid < 64) {
            const int rb = (i - 1) & 1;
            const float4 A  = *reinterpret_cast<const float4*>(&s_rp[rb][tid * 4]);
            const float4 Bv = *reinterpret_cast<const float4*>(&s_rp[rb][256 + tid * 4]);
            float4 S;
            S.x = A.x + Bv.x; S.y = A.y + Bv.y; S.z = A.z + Bv.z; S.w = A.w + Bv.w;
            *reinterpret_cast<float4*>(&s_r[rb][tid * 4]) = S;
        }

        // ---- B(i-2): f-partials = Wf[f, g-quarter] . r -------------------
        if (i >= 2 && i <= SS + 1) {
            const int bb = (i - 2) & 1;
            ull acc0 = 0ull, acc1 = 0ull;
            const ulonglong2* sr2 =
                reinterpret_cast<const ulonglong2*>(&s_r[bb][g * 64]);
            #pragma unroll
            for (int j4 = 0; j4 < 16; j4++) {
                const ulonglong2 rp = sr2[j4];
                acc0 = fma2(wfr[2 * j4],     rp.x, acc0);
                acc1 = fma2(wfr[2 * j4 + 1], rp.y, acc1);
            }
            float y0, y1, y2, y3;
            upk2(acc0, y0, y1); upk2(acc1, y2, y3);
            s_fp[bb][g * 128 + f] = (y0 + y1) + (y2 + y3);
        }

        // ---- E(i-3): tanh + Wp + reduce + accumulate ---------------------
        if (i >= 3 && tid < FD) {
            const int eb = (i - 3) & 1;
            const float pre = s_fp[eb][f] + s_fp[eb][128 + f]
                            + s_fp[eb][256 + f] + s_fp[eb][384 + f] + fk_c;
            float term = wp_f * tanhf(pre);
            #pragma unroll
            for (int o = 16; o > 0; o >>= 1)
                term += __shfl_xor_sync(0xffffffffu, term, o);
            if ((tid & 31) == 0) atomicAdd(out + b * SS + (i - 3), term);
        }

        // ---- commit prefetches, single barrier ---------------------------
        if (tid < MSZ) s_w[buf ^ 1][tid] = w_pf;
        e_c = e_pf; a_c = a_pf; fk_c = fk_pf;
        __syncthreads();
    }
}

// ---------------------------------------------------------------------------
// Launch. Inputs: q, qa, k_emb, v_emb, Wf, bf, Wp, bp, We, be, Wa, ba, Mk, Mv0
// ---------------------------------------------------------------------------
extern "C" void kernel_launch(void* const* d_in, const int* in_sizes, int n_in,
                              void* d_out, int out_size)
{
    const int*   q     = (const int*)  d_in[0];
    const int*   qa    = (const int*)  d_in[1];
    const float* k_emb = (const float*)d_in[2];
    const float* v_emb = (const float*)d_in[3];
    const float* Wf    = (const float*)d_in[4];
    const float* bf    = (const float*)d_in[5];
    const float* Wp    = (const float*)d_in[6];
    const float* bp    = (const float*)d_in[7];
    const float* We    = (const float*)d_in[8];
    const float* be    = (const float*)d_in[9];
    const float* Wa    = (const float*)d_in[10];
    const float* ba    = (const float*)d_in[11];
    const float* Mk    = (const float*)d_in[12];
    const float* Mv0   = (const float*)d_in[13];
    float* out = (float*)d_out;

    cudaFuncSetAttribute(build_wfk_kernel,
                         cudaFuncAttributeMaxDynamicSharedMemorySize, WFK_SMEM);

    transpose_we_wa<<<dim3(8, 8, 2), dim3(32, 8)>>>(We, Wa);
    build_wfk_kernel<<<(NQ1 + WTI - 1) / WTI, 256, WFK_SMEM>>>(k_emb, Mk, Wf, bf);
    build_ea_kernel<<<(NQA1 + TI - 1) / TI, 256>>>(v_emb, be, ba);
    init_out_kernel<<<(BB * SS + 255) / 256, 256>>>(out, bp);
    dkvmn_main_kernel<<<BB, 512>>>(q, qa, Wf, Wp, Mv0, out);
}

// round 4
// speedup vs baseline: 1.5138x; 1.5138x over previous
#include <cuda_runtime.h>
#include <cstdint>

// Problem dims (fixed by dataset)
#define NQ1   10001
#define NQA1  20001
#define MSZ   64
#define KD    128
#define VD    256
#define VM    256
#define FD    128
#define BB    512
#define SS    512

typedef unsigned long long ull;

// ---------------------------------------------------------------------------
// f32x2 packed-math helpers
// ---------------------------------------------------------------------------
__device__ __forceinline__ ull pk2(float a, float b) {
    ull r; asm("mov.b64 %0, {%1, %2};" : "=l"(r) : "f"(a), "f"(b)); return r;
}
__device__ __forceinline__ void upk2(ull p, float& a, float& b) {
    asm("mov.b64 {%0, %1}, %2;" : "=f"(a), "=f"(b) : "l"(p));
}
__device__ __forceinline__ ull fma2(ull a, ull b, ull c) {
    ull d; asm("fma.rn.f32x2 %0, %1, %2, %3;" : "=l"(d) : "l"(a), "l"(b), "l"(c)); return d;
}

// ---------------------------------------------------------------------------
// Scratch tables
// ---------------------------------------------------------------------------
__device__ float g_wtab [NQ1  * MSZ];
__device__ float g_fktab[NQ1  * FD ];
__device__ float g_etab [NQA1 * VM ];
__device__ float g_atab [NQA1 * VM ];
__device__ float g_WeT  [VD * VM];
__device__ float g_WaT  [VD * VM];

// ---------------------------------------------------------------------------
// Transpose We/Wa (256x256) into [j][u] layout
// ---------------------------------------------------------------------------
__global__ void transpose_we_wa(const float* __restrict__ We,
                                const float* __restrict__ Wa)
{
    __shared__ float tile[32][33];
    const float* src = blockIdx.z ? Wa : We;
    float* dst = blockIdx.z ? g_WaT : g_WeT;
    const int bx = blockIdx.x * 32;
    const int by = blockIdx.y * 32;
    #pragma unroll
    for (int k = 0; k < 4; k++)
        tile[threadIdx.y + k * 8][threadIdx.x] =
            src[(by + threadIdx.y + k * 8) * VD + bx + threadIdx.x];
    __syncthreads();
    #pragma unroll
    for (int k = 0; k < 4; k++)
        dst[(bx + threadIdx.y + k * 8) * VM + by + threadIdx.x] =
            tile[threadIdx.x][threadIdx.y + k * 8];
}

// ---------------------------------------------------------------------------
// Kernel A: per-q tables (32 indices/block, coalesced + conflict-free)
// ---------------------------------------------------------------------------
#define WTI 32
#define WFK_SMEM ((WTI*KD + MSZ*132 + FD*132 + WTI*MSZ) * 4)

__global__ void __launch_bounds__(256)
build_wfk_kernel(const float* __restrict__ k_emb, const float* __restrict__ Mk,
                 const float* __restrict__ Wf,    const float* __restrict__ bf)
{
    extern __shared__ float sm[];
    float* k_s   = sm;
    float* Mk_s  = sm + WTI * KD;
    float* Wfk_s = Mk_s + MSZ * 132;
    float* sc_s  = Wfk_s + FD * 132;

    const int tid  = threadIdx.x;
    const int base = blockIdx.x * WTI;

    for (int idx = tid; idx < WTI * KD; idx += 256) {
        const int i = idx >> 7, j = idx & 127;
        const int gi = min(base + i, NQ1 - 1);
        k_s[i * KD + j] = k_emb[gi * KD + j];
    }
    for (int idx = tid; idx < MSZ * KD; idx += 256) {
        const int m = idx >> 7, j = idx & 127;
        Mk_s[m * 132 + j] = Mk[idx];
    }
    for (int idx = tid; idx < FD * KD; idx += 256) {
        const int ff = idx >> 7, j = idx & 127;
        Wfk_s[ff * 132 + j] = Wf[ff * (KD + VM) + VM + j];
    }
    __syncthreads();

    {
        const int m = tid & 63, ig = tid >> 6;
        float acc[8];
        #pragma unroll
        for (int ii = 0; ii < 8; ii++) acc[ii] = 0.f;
        #pragma unroll 4
        for (int j4 = 0; j4 < KD / 4; j4++) {
            const float4 mk = *reinterpret_cast<const float4*>(Mk_s + m * 132 + j4 * 4);
            #pragma unroll
            for (int ii = 0; ii < 8; ii++) {
                const float4 kv = *reinterpret_cast<const float4*>(k_s + (ig * 8 + ii) * KD + j4 * 4);
                acc[ii] = fmaf(mk.x, kv.x, fmaf(mk.y, kv.y, fmaf(mk.z, kv.z, fmaf(mk.w, kv.w, acc[ii]))));
            }
        }
        #pragma unroll
        for (int ii = 0; ii < 8; ii++) sc_s[(ig * 8 + ii) * MSZ + m] = acc[ii];
    }
    __syncthreads();

    {
        const int lane = tid & 31, w = tid >> 5;
        #pragma unroll
        for (int rep = 0; rep < 4; rep++) {
            const int i = w + rep * 8;
            const float sa = sc_s[i * MSZ + lane];
            const float sb = sc_s[i * MSZ + 32 + lane];
            float mx = fmaxf(sa, sb);
            #pragma unroll
            for (int o = 16; o > 0; o >>= 1) mx = fmaxf(mx, __shfl_xor_sync(0xffffffffu, mx, o));
            const float ea = expf(sa - mx), eb = expf(sb - mx);
            float s = ea + eb;
            #pragma unroll
            for (int o = 16; o > 0; o >>= 1) s += __shfl_xor_sync(0xffffffffu, s, o);
            const float inv = 1.f / s;
            const int gi = base + i;
            if (gi < NQ1) {
                g_wtab[gi * MSZ + lane]      = ea * inv;
                g_wtab[gi * MSZ + 32 + lane] = eb * inv;
            }
        }
    }

    {
        const int ff = tid & 127, h = tid >> 7;
        float fa[16];
        #pragma unroll
        for (int ii = 0; ii < 16; ii++) fa[ii] = 0.f;
        #pragma unroll 2
        for (int j4 = 0; j4 < KD / 4; j4++) {
            const float4 wv = *reinterpret_cast<const float4*>(Wfk_s + ff * 132 + j4 * 4);
            #pragma unroll
            for (int ii = 0; ii < 16; ii++) {
                const float4 kv = *reinterpret_cast<const float4*>(k_s + (h * 16 + ii) * KD + j4 * 4);
                fa[ii] = fmaf(wv.x, kv.x, fmaf(wv.y, kv.y, fmaf(wv.z, kv.z, fmaf(wv.w, kv.w, fa[ii]))));
            }
        }
        const float bff = bf[ff];
        #pragma unroll
        for (int ii = 0; ii < 16; ii++) {
            const int gi = base + h * 16 + ii;
            if (gi < NQ1) g_fktab[gi * FD + ff] = fa[ii] + bff;
        }
    }
}

// ---------------------------------------------------------------------------
// Kernel B: per-qa tables from transposed weights
// ---------------------------------------------------------------------------
#define TI 32
__global__ void __launch_bounds__(256)
build_ea_kernel(const float* __restrict__ v_emb,
                const float* __restrict__ be, const float* __restrict__ ba)
{
    __shared__ float4 v_s[TI * (VD / 4)];
    const int tid  = threadIdx.x;
    const int base = blockIdx.x * TI;

    for (int idx = tid; idx < TI * (VD / 4); idx += 256) {
        const int i = idx >> 6, j4 = idx & 63;
        const int gi = min(base + i, NQA1 - 1);
        v_s[i * (VD / 4) + j4] = reinterpret_cast<const float4*>(v_emb)[gi * (VD / 4) + j4];
    }
    __syncthreads();

    const int u = tid;
    float acce[TI], acca[TI];
    #pragma unroll
    for (int i = 0; i < TI; i++) { acce[i] = 0.f; acca[i] = 0.f; }

    #pragma unroll 1
    for (int j4 = 0; j4 < VD / 4; j4++) {
        const int j = j4 * 4;
        const float we0 = g_WeT[(j + 0) * VM + u];
        const float we1 = g_WeT[(j + 1) * VM + u];
        const float we2 = g_WeT[(j + 2) * VM + u];
        const float we3 = g_WeT[(j + 3) * VM + u];
        const float wa0 = g_WaT[(j + 0) * VM + u];
        const float wa1 = g_WaT[(j + 1) * VM + u];
        const float wa2 = g_WaT[(j + 2) * VM + u];
        const float wa3 = g_WaT[(j + 3) * VM + u];
        #pragma unroll
        for (int i = 0; i < TI; i++) {
            const float4 v = v_s[i * (VD / 4) + j4];
            acce[i] = fmaf(we0, v.x, fmaf(we1, v.y, fmaf(we2, v.z, fmaf(we3, v.w, acce[i]))));
            acca[i] = fmaf(wa0, v.x, fmaf(wa1, v.y, fmaf(wa2, v.z, fmaf(wa3, v.w, acca[i]))));
        }
    }

    const float bei = be[u], bai = ba[u];
    #pragma unroll
    for (int i = 0; i < TI; i++) {
        const int gi = base + i;
        if (gi < NQA1) {
            g_etab[gi * VM + u] = 1.f / (1.f + expf(-(acce[i] + bei)));
            g_atab[gi * VM + u] = tanhf(acca[i] + bai);
        }
    }
}

__global__ void init_out_kernel(float* __restrict__ out, const float* __restrict__ bp)
{
    const int i = blockIdx.x * 256 + threadIdx.x;
    if (i < BB * SS) out[i] = bp[0];
}

// ---------------------------------------------------------------------------
// Main kernel: 256 threads, R2 data layout, 4 steps per barrier span.
//   span s: [A(4s..4s+3) + E(span s-1)] -> bar -> [B(4s..4s+3) + commit] -> bar
//   0.5 barriers/step; E reads prev-span double-buffered s_fp.
// ---------------------------------------------------------------------------
#define TSP 4
#define NSP (SS / TSP)
#define STG 258                      // padded Wf staging stride

// dynamic smem layout (floats)
#define O_W    0                                  // s_w [2][TSP][64]
#define O_R    (O_W + 2 * TSP * MSZ)              // s_r [2][TSP][256]
#define O_FP   (O_R + 2 * TSP * VM)               // s_fp[2][TSP][256]
#define O_Q    (O_FP + 2 * TSP * VM)              // s_q [512] (int)
#define O_QA   (O_Q + SS)
#define O_STAGE (O_QA + SS)                       // 32*258
#define MAIN_SMEM ((O_STAGE + 32 * STG) * 4)

__global__ void __launch_bounds__(256, 1)
dkvmn_main_kernel(const int* __restrict__ q,  const int* __restrict__ qa,
                  const float* __restrict__ Wf, const float* __restrict__ Wp,
                  const float* __restrict__ Mv0, float* __restrict__ out)
{
    extern __shared__ __align__(16) float smf[];
    float* s_w     = smf + O_W;     // [2][TSP][64]
    float* s_r     = smf + O_R;     // [2][TSP][256]
    float* s_fp    = smf + O_FP;    // [2][TSP][256]
    int*   s_q     = reinterpret_cast<int*>(smf + O_Q);
    int*   s_qa    = reinterpret_cast<int*>(smf + O_QA);
    float* s_stage = smf + O_STAGE;

    const int b   = blockIdx.x;
    const int tid = threadIdx.x;
    const int f   = tid & 127;
    const int h   = tid >> 7;

    for (int idx = tid; idx < SS; idx += 256) {
        s_q [idx] = q [b * SS + idx];
        s_qa[idx] = qa[b * SS + idx];
    }

    // ---- Wf_r -> registers via coalesced smem bounce (padded stride) ------
    ull wfr[64];
    #pragma unroll 1
    for (int c = 0; c < 4; c++) {
        if (c) __syncthreads();
        for (int idx = tid; idx < 32 * VM; idx += 256) {
            const int fr = idx >> 8, uu = idx & 255;
            s_stage[fr * STG + uu] = Wf[(c * 32 + fr) * (KD + VM) + uu];
        }
        __syncthreads();
        if ((f >> 5) == c) {
            const ull* p = reinterpret_cast<const ull*>(s_stage + (f & 31) * STG + h * 128);
            #pragma unroll
            for (int j2 = 0; j2 < 64; j2++) wfr[j2] = p[j2];
        }
    }

    // ---- state: Mv[:,tid] as 32 packed pairs ------------------------------
    ull mv2[32];
    #pragma unroll
    for (int m2 = 0; m2 < 32; m2++)
        mv2[m2] = pk2(Mv0[(2 * m2) * VM + tid], Mv0[(2 * m2 + 1) * VM + tid]);

    const float wp_f = Wp[f];
    __syncthreads();

    // ---- initial tables for span 0 ----------------------------------------
    float e_c[TSP], a_c[TSP], fkE[TSP];
    #pragma unroll
    for (int j = 0; j < TSP; j++) {
        const int qt = s_q[j], qat = s_qa[j];
        e_c[j] = g_etab[qat * VM + tid];
        a_c[j] = g_atab[qat * VM + tid];
        fkE[j] = 0.f;
        if (tid < MSZ) s_w[(0) * TSP * MSZ + j * MSZ + tid] = g_wtab[qt * MSZ + tid];
    }
    __syncthreads();

    #pragma unroll 1
    for (int s = 0; s < NSP; s++) {
        const int p = s & 1;
        float* swp  = s_w  + p * TSP * MSZ;
        float* srp  = s_r  + p * TSP * VM;
        float* sfpp = s_fp + p * TSP * VM;

        // ---- prefetch: e/a/w for span s+1, fk for span s ------------------
        const int sn = (s + 1 < NSP) ? s + 1 : s;
        float e_n[TSP], a_n[TSP], fk_pf[TSP], w_n[TSP];
        #pragma unroll
        for (int j = 0; j < TSP; j++) {
            const int qn = s_q[sn * TSP + j], qan = s_qa[sn * TSP + j];
            e_n[j] = g_etab[qan * VM + tid];
            a_n[j] = g_atab[qan * VM + tid];
            if (tid < MSZ) w_n[j] = g_wtab[qn * MSZ + tid];
            fk_pf[j] = g_fktab[s_q[s * TSP + j] * FD + f];
        }

        // ---- Phase A x4 ---------------------------------------------------
        #pragma unroll
        for (int j = 0; j < TSP; j++) {
            const ull ne2 = pk2(-e_c[j], -e_c[j]);
            const ull a2  = pk2(a_c[j], a_c[j]);
            ull r0 = 0ull, r1 = 0ull, r2 = 0ull, r3 = 0ull;
            const ulonglong2* sw2 =
                reinterpret_cast<const ulonglong2*>(swp + j * MSZ);
            #pragma unroll
            for (int m4 = 0; m4 < 16; m4++) {
                const ulonglong2 wp = sw2[m4];
                const ull mA = mv2[2 * m4], mB = mv2[2 * m4 + 1];
                if (m4 & 1) { r2 = fma2(wp.x, mA, r2); r3 = fma2(wp.y, mB, r3); }
                else        { r0 = fma2(wp.x, mA, r0); r1 = fma2(wp.y, mB, r1); }
                const ull tA = fma2(ne2, mA, a2);
                const ull tB = fma2(ne2, mB, a2);
                mv2[2 * m4]     = fma2(wp.x, tA, mA);
                mv2[2 * m4 + 1] = fma2(wp.y, tB, mB);
            }
            float x0, x1, x2, x3, x4, x5, x6, x7;
            upk2(r0, x0, x1); upk2(r1, x2, x3);
            upk2(r2, x4, x5); upk2(r3, x6, x7);
            srp[j * VM + tid] = ((x0 + x1) + (x2 + x3)) + ((x4 + x5) + (x6 + x7));
        }

        // ---- Phase E for span s-1 (reads other-parity s_fp) ---------------
        if (s > 0 && tid < FD) {
            const float* sfq = s_fp + (p ^ 1) * TSP * VM;
            #pragma unroll
            for (int j = 0; j < TSP; j++) {
                const float pre = sfq[j * VM + f] + sfq[j * VM + 128 + f] + fkE[j];
                float term = wp_f * tanhf(pre);
                #pragma unroll
                for (int o = 16; o > 0; o >>= 1)
                    term += __shfl_xor_sync(0xffffffffu, term, o);
                if ((tid & 31) == 0)
                    atomicAdd(out + b * SS + (s - 1) * TSP + j, term);
            }
        }
        __syncthreads();                       // s_r(p) ready

        // ---- Phase B x4 ---------------------------------------------------
        #pragma unroll
        for (int j = 0; j < TSP; j++) {
            ull acc0 = 0ull, acc1 = 0ull;
            const ulonglong2* sr2 =
                reinterpret_cast<const ulonglong2*>(srp + j * VM + h * 128);
            #pragma unroll
            for (int j4 = 0; j4 < 32; j4++) {
                const ulonglong2 rp = sr2[j4];
                acc0 = fma2(wfr[2 * j4],     rp.x, acc0);
                acc1 = fma2(wfr[2 * j4 + 1], rp.y, acc1);
            }
            float y0, y1, y2, y3;
            upk2(acc0, y0, y1); upk2(acc1, y2, y3);
            sfpp[j * VM + h * 128 + f] = (y0 + y1) + (y2 + y3);
        }

        // ---- commit prefetches --------------------------------------------
        #pragma unroll
        for (int j = 0; j < TSP; j++) {
            e_c[j] = e_n[j]; a_c[j] = a_n[j]; fkE[j] = fk_pf[j];
        }
        if (tid < MSZ) {
            float* swn = s_w + (p ^ 1) * TSP * MSZ;
            #pragma unroll
            for (int j = 0; j < TSP; j++) swn[j * MSZ + tid] = w_n[j];
        }
        __syncthreads();                       // span boundary
    }

    // ---- epilogue: E for last span ----------------------------------------
    if (tid < FD) {
        const float* sfq = s_fp + ((NSP - 1) & 1) * TSP * VM;
        #pragma unroll
        for (int j = 0; j < TSP; j++) {
            const float pre = sfq[j * VM + f] + sfq[j * VM + 128 + f] + fkE[j];
            float term = wp_f * tanhf(pre);
            #pragma unroll
            for (int o = 16; o > 0; o >>= 1)
                term += __shfl_xor_sync(0xffffffffu, term, o);
            if ((tid & 31) == 0)
                atomicAdd(out + b * SS + (NSP - 1) * TSP + j, term);
        }
    }
}

// ---------------------------------------------------------------------------
// Launch. Inputs: q, qa, k_emb, v_emb, Wf, bf, Wp, bp, We, be, Wa, ba, Mk, Mv0
// ---------------------------------------------------------------------------
extern "C" void kernel_launch(void* const* d_in, const int* in_sizes, int n_in,
                              void* d_out, int out_size)
{
    const int*   q     = (const int*)  d_in[0];
    const int*   qa    = (const int*)  d_in[1];
    const float* k_emb = (const float*)d_in[2];
    const float* v_emb = (const float*)d_in[3];
    const float* Wf    = (const float*)d_in[4];
    const float* bf    = (const float*)d_in[5];
    const float* Wp    = (const float*)d_in[6];
    const float* bp    = (const float*)d_in[7];
    const float* We    = (const float*)d_in[8];
    const float* be    = (const float*)d_in[9];
    const float* Wa    = (const float*)d_in[10];
    const float* ba    = (const float*)d_in[11];
    const float* Mk    = (const float*)d_in[12];
    const float* Mv0   = (const float*)d_in[13];
    float* out = (float*)d_out;

    cudaFuncSetAttribute(build_wfk_kernel,
                         cudaFuncAttributeMaxDynamicSharedMemorySize, WFK_SMEM);
    cudaFuncSetAttribute(dkvmn_main_kernel,
                         cudaFuncAttributeMaxDynamicSharedMemorySize, MAIN_SMEM);

    transpose_we_wa<<<dim3(8, 8, 2), dim3(32, 8)>>>(We, Wa);
    build_wfk_kernel<<<(NQ1 + WTI - 1) / WTI, 256, WFK_SMEM>>>(k_emb, Mk, Wf, bf);
    build_ea_kernel<<<(NQA1 + TI - 1) / TI, 256>>>(v_emb, be, ba);
    init_out_kernel<<<(BB * SS + 255) / 256, 256>>>(out, bp);
    dkvmn_main_kernel<<<BB, 256, MAIN_SMEM>>>(q, qa, Wf, Wp, Mv0, out);
}

// round 5
// speedup vs baseline: 1.6612x; 1.0974x over previous
#include <cuda_runtime.h>
#include <cstdint>

// Problem dims (fixed by dataset)
#define NQ1   10001
#define NQA1  20001
#define MSZ   64
#define KD    128
#define VD    256
#define VM    256
#define FD    128
#define BB    512
#define SS    512

typedef unsigned long long ull;

// ---------------------------------------------------------------------------
// f32x2 packed-math + cp.async helpers
// ---------------------------------------------------------------------------
__device__ __forceinline__ ull pk2(float a, float b) {
    ull r; asm("mov.b64 %0, {%1, %2};" : "=l"(r) : "f"(a), "f"(b)); return r;
}
__device__ __forceinline__ void upk2(ull p, float& a, float& b) {
    asm("mov.b64 {%0, %1}, %2;" : "=f"(a), "=f"(b) : "l"(p));
}
__device__ __forceinline__ ull fma2(ull a, ull b, ull c) {
    ull d; asm("fma.rn.f32x2 %0, %1, %2, %3;" : "=l"(d) : "l"(a), "l"(b), "l"(c)); return d;
}
__device__ __forceinline__ uint32_t s2u(const void* p) {
    uint32_t a;
    asm("{ .reg .u64 t; cvta.to.shared.u64 t, %1; cvt.u32.u64 %0, t; }" : "=r"(a) : "l"(p));
    return a;
}
__device__ __forceinline__ void cpa4(uint32_t s, const void* g) {
    asm volatile("cp.async.ca.shared.global [%0], [%1], 4;" :: "r"(s), "l"(g));
}
#define CPA_COMMIT() asm volatile("cp.async.commit_group;" ::: "memory")
#define CPA_WAIT0()  asm volatile("cp.async.wait_group 0;"  ::: "memory")

// ---------------------------------------------------------------------------
// Scratch tables
// ---------------------------------------------------------------------------
__device__ float g_wtab [NQ1  * MSZ];
__device__ float g_fktab[NQ1  * FD ];
__device__ float g_etab [NQA1 * VM ];
__device__ float g_atab [NQA1 * VM ];
__device__ float g_WeT  [VD * VM];
__device__ float g_WaT  [VD * VM];

// ---------------------------------------------------------------------------
// Transpose We/Wa (256x256) into [j][u] layout
// ---------------------------------------------------------------------------
__global__ void transpose_we_wa(const float* __restrict__ We,
                                const float* __restrict__ Wa)
{
    __shared__ float tile[32][33];
    const float* src = blockIdx.z ? Wa : We;
    float* dst = blockIdx.z ? g_WaT : g_WeT;
    const int bx = blockIdx.x * 32;
    const int by = blockIdx.y * 32;
    #pragma unroll
    for (int k = 0; k < 4; k++)
        tile[threadIdx.y + k * 8][threadIdx.x] =
            src[(by + threadIdx.y + k * 8) * VD + bx + threadIdx.x];
    __syncthreads();
    #pragma unroll
    for (int k = 0; k < 4; k++)
        dst[(bx + threadIdx.y + k * 8) * VM + by + threadIdx.x] =
            tile[threadIdx.x][threadIdx.y + k * 8];
}

// ---------------------------------------------------------------------------
// Kernel A: per-q tables (32 indices/block, coalesced + conflict-free)
// ---------------------------------------------------------------------------
#define WTI 32
#define WFK_SMEM ((WTI*KD + MSZ*132 + FD*132 + WTI*MSZ) * 4)

__global__ void __launch_bounds__(256)
build_wfk_kernel(const float* __restrict__ k_emb, const float* __restrict__ Mk,
                 const float* __restrict__ Wf,    const float* __restrict__ bf)
{
    extern __shared__ float sm[];
    float* k_s   = sm;
    float* Mk_s  = sm + WTI * KD;
    float* Wfk_s = Mk_s + MSZ * 132;
    float* sc_s  = Wfk_s + FD * 132;

    const int tid  = threadIdx.x;
    const int base = blockIdx.x * WTI;

    for (int idx = tid; idx < WTI * KD; idx += 256) {
        const int i = idx >> 7, j = idx & 127;
        const int gi = min(base + i, NQ1 - 1);
        k_s[i * KD + j] = k_emb[gi * KD + j];
    }
    for (int idx = tid; idx < MSZ * KD; idx += 256) {
        const int m = idx >> 7, j = idx & 127;
        Mk_s[m * 132 + j] = Mk[idx];
    }
    for (int idx = tid; idx < FD * KD; idx += 256) {
        const int ff = idx >> 7, j = idx & 127;
        Wfk_s[ff * 132 + j] = Wf[ff * (KD + VM) + VM + j];
    }
    __syncthreads();

    {
        const int m = tid & 63, ig = tid >> 6;
        float acc[8];
        #pragma unroll
        for (int ii = 0; ii < 8; ii++) acc[ii] = 0.f;
        #pragma unroll 4
        for (int j4 = 0; j4 < KD / 4; j4++) {
            const float4 mk = *reinterpret_cast<const float4*>(Mk_s + m * 132 + j4 * 4);
            #pragma unroll
            for (int ii = 0; ii < 8; ii++) {
                const float4 kv = *reinterpret_cast<const float4*>(k_s + (ig * 8 + ii) * KD + j4 * 4);
                acc[ii] = fmaf(mk.x, kv.x, fmaf(mk.y, kv.y, fmaf(mk.z, kv.z, fmaf(mk.w, kv.w, acc[ii]))));
            }
        }
        #pragma unroll
        for (int ii = 0; ii < 8; ii++) sc_s[(ig * 8 + ii) * MSZ + m] = acc[ii];
    }
    __syncthreads();

    {
        const int lane = tid & 31, w = tid >> 5;
        #pragma unroll
        for (int rep = 0; rep < 4; rep++) {
            const int i = w + rep * 8;
            const float sa = sc_s[i * MSZ + lane];
            const float sb = sc_s[i * MSZ + 32 + lane];
            float mx = fmaxf(sa, sb);
            #pragma unroll
            for (int o = 16; o > 0; o >>= 1) mx = fmaxf(mx, __shfl_xor_sync(0xffffffffu, mx, o));
            const float ea = expf(sa - mx), eb = expf(sb - mx);
            float s = ea + eb;
            #pragma unroll
            for (int o = 16; o > 0; o >>= 1) s += __shfl_xor_sync(0xffffffffu, s, o);
            const float inv = 1.f / s;
            const int gi = base + i;
            if (gi < NQ1) {
                g_wtab[gi * MSZ + lane]      = ea * inv;
                g_wtab[gi * MSZ + 32 + lane] = eb * inv;
            }
        }
    }

    {
        const int ff = tid & 127, h = tid >> 7;
        float fa[16];
        #pragma unroll
        for (int ii = 0; ii < 16; ii++) fa[ii] = 0.f;
        #pragma unroll 2
        for (int j4 = 0; j4 < KD / 4; j4++) {
            const float4 wv = *reinterpret_cast<const float4*>(Wfk_s + ff * 132 + j4 * 4);
            #pragma unroll
            for (int ii = 0; ii < 16; ii++) {
                const float4 kv = *reinterpret_cast<const float4*>(k_s + (h * 16 + ii) * KD + j4 * 4);
                fa[ii] = fmaf(wv.x, kv.x, fmaf(wv.y, kv.y, fmaf(wv.z, kv.z, fmaf(wv.w, kv.w, fa[ii]))));
            }
        }
        const float bff = bf[ff];
        #pragma unroll
        for (int ii = 0; ii < 16; ii++) {
            const int gi = base + h * 16 + ii;
            if (gi < NQ1) g_fktab[gi * FD + ff] = fa[ii] + bff;
        }
    }
}

// ---------------------------------------------------------------------------
// Kernel B: per-qa tables from transposed weights
// ---------------------------------------------------------------------------
#define TI 32
__global__ void __launch_bounds__(256)
build_ea_kernel(const float* __restrict__ v_emb,
                const float* __restrict__ be, const float* __restrict__ ba)
{
    __shared__ float4 v_s[TI * (VD / 4)];
    const int tid  = threadIdx.x;
    const int base = blockIdx.x * TI;

    for (int idx = tid; idx < TI * (VD / 4); idx += 256) {
        const int i = idx >> 6, j4 = idx & 63;
        const int gi = min(base + i, NQA1 - 1);
        v_s[i * (VD / 4) + j4] = reinterpret_cast<const float4*>(v_emb)[gi * (VD / 4) + j4];
    }
    __syncthreads();

    const int u = tid;
    float acce[TI], acca[TI];
    #pragma unroll
    for (int i = 0; i < TI; i++) { acce[i] = 0.f; acca[i] = 0.f; }

    #pragma unroll 1
    for (int j4 = 0; j4 < VD / 4; j4++) {
        const int j = j4 * 4;
        const float we0 = g_WeT[(j + 0) * VM + u];
        const float we1 = g_WeT[(j + 1) * VM + u];
        const float we2 = g_WeT[(j + 2) * VM + u];
        const float we3 = g_WeT[(j + 3) * VM + u];
        const float wa0 = g_WaT[(j + 0) * VM + u];
        const float wa1 = g_WaT[(j + 1) * VM + u];
        const float wa2 = g_WaT[(j + 2) * VM + u];
        const float wa3 = g_WaT[(j + 3) * VM + u];
        #pragma unroll
        for (int i = 0; i < TI; i++) {
            const float4 v = v_s[i * (VD / 4) + j4];
            acce[i] = fmaf(we0, v.x, fmaf(we1, v.y, fmaf(we2, v.z, fmaf(we3, v.w, acce[i]))));
            acca[i] = fmaf(wa0, v.x, fmaf(wa1, v.y, fmaf(wa2, v.z, fmaf(wa3, v.w, acca[i]))));
        }
    }

    const float bei = be[u], bai = ba[u];
    #pragma unroll
    for (int i = 0; i < TI; i++) {
        const int gi = base + i;
        if (gi < NQA1) {
            g_etab[gi * VM + u] = 1.f / (1.f + expf(-(acce[i] + bei)));
            g_atab[gi * VM + u] = tanhf(acca[i] + bai);
        }
    }
}

// ---------------------------------------------------------------------------
// Main kernel: 256 threads, 4 steps/span, cp.async gate streaming (no
// prefetch registers), no atomics, direct output stores.
//   span s: [A x4 (reads s_e/s_a/s_w[p]) + E(span s-1)] -> bar
//           [B x4 -> s_fp + out-store(span s-1)] -> cp.wait -> bar
// ---------------------------------------------------------------------------
#define TSP 4
#define NSP (SS / TSP)
#define STG 258

// smem layout (floats)
#define O_E     0                               // [2][TSP][256]
#define O_A     (O_E  + 2 * TSP * VM)           // [2][TSP][256]
#define O_WW    (O_A  + 2 * TSP * VM)           // [2][TSP][64]
#define O_FK    (O_WW + 2 * TSP * MSZ)          // [2][TSP][128]
#define O_R     (O_FK + 2 * TSP * FD)           // [TSP][256]
#define O_FP    (O_R  + TSP * VM)               // [TSP][256]
#define O_RED   (O_FP + TSP * VM)               // [TSP][4]
#define O_Q     (O_RED + TSP * 4)               // [512] int
#define O_QA    (O_Q + SS)
#define O_STAGE (O_QA + SS)                     // 32*258
#define MAIN_SMEM ((O_STAGE + 32 * STG) * 4)

__global__ void __launch_bounds__(256, 1)
dkvmn_main_kernel(const int* __restrict__ q,  const int* __restrict__ qa,
                  const float* __restrict__ Wf, const float* __restrict__ Wp,
                  const float* __restrict__ bp, const float* __restrict__ Mv0,
                  float* __restrict__ out)
{
    extern __shared__ __align__(16) float smf[];
    float* s_e     = smf + O_E;
    float* s_a     = smf + O_A;
    float* s_w     = smf + O_WW;
    float* s_fk    = smf + O_FK;
    float* s_r     = smf + O_R;
    float* s_fp    = smf + O_FP;
    float* s_red   = smf + O_RED;
    int*   s_q     = reinterpret_cast<int*>(smf + O_Q);
    int*   s_qa    = reinterpret_cast<int*>(smf + O_QA);
    float* s_stage = smf + O_STAGE;

    const int b   = blockIdx.x;
    const int tid = threadIdx.x;
    const int f   = tid & 127;
    const int h   = tid >> 7;

    const uint32_t u_e  = s2u(s_e)  + tid * 4;
    const uint32_t u_a  = s2u(s_a)  + tid * 4;
    const uint32_t u_w  = s2u(s_w)  + tid * 4;
    const uint32_t u_fk = s2u(s_fk) + tid * 4;

    for (int idx = tid; idx < SS; idx += 256) {
        s_q [idx] = q [b * SS + idx];
        s_qa[idx] = qa[b * SS + idx];
    }

    // ---- Wf_r -> registers via coalesced smem bounce ----------------------
    ull wfr[64];
    #pragma unroll 1
    for (int c = 0; c < 4; c++) {
        if (c) __syncthreads();
        for (int idx = tid; idx < 32 * VM; idx += 256) {
            const int fr = idx >> 8, uu = idx & 255;
            s_stage[fr * STG + uu] = Wf[(c * 32 + fr) * (KD + VM) + uu];
        }
        __syncthreads();
        if ((f >> 5) == c) {
            const ull* p = reinterpret_cast<const ull*>(s_stage + (f & 31) * STG + h * 128);
            #pragma unroll
            for (int j2 = 0; j2 < 64; j2++) wfr[j2] = p[j2];
        }
    }

    // ---- state: Mv[:,tid] as 32 packed pairs ------------------------------
    ull mv2[32];
    #pragma unroll
    for (int m2 = 0; m2 < 32; m2++)
        mv2[m2] = pk2(Mv0[(2 * m2) * VM + tid], Mv0[(2 * m2 + 1) * VM + tid]);

    const float wp_f = Wp[f];
    const float bp0  = bp[0];
    __syncthreads();   // s_q/s_qa ready

    // ---- load span-0 gates into parity-0 buffers (synchronous) ------------
    #pragma unroll
    for (int j = 0; j < TSP; j++) {
        const int qt = s_q[j], qat = s_qa[j];
        s_e[j * VM + tid] = g_etab[qat * VM + tid];
        s_a[j * VM + tid] = g_atab[qat * VM + tid];
        if (tid < MSZ) s_w[j * MSZ + tid] = g_wtab[qt * MSZ + tid];
    }
    __syncthreads();

    #pragma unroll 1
    for (int s = 0; s < NSP; s++) {
        const int p  = s & 1;
        const int pn = p ^ 1;

        // ---- cp.async prefetch: gates(span s+1) -> parity pn; fk(span s) -> parity p
        {
            const int sn = (s + 1 < NSP) ? s + 1 : s;
            #pragma unroll
            for (int j = 0; j < TSP; j++) {
                const int qan = s_qa[sn * TSP + j];
                cpa4(u_e + (pn * TSP + j) * VM * 4, g_etab + qan * VM + tid);
                cpa4(u_a + (pn * TSP + j) * VM * 4, g_atab + qan * VM + tid);
            }
            if (tid < MSZ) {
                #pragma unroll
                for (int j = 0; j < TSP; j++)
                    cpa4(u_w + (pn * TSP + j) * MSZ * 4,
                         g_wtab + s_q[sn * TSP + j] * MSZ + tid);
            }
            if (tid < FD) {
                #pragma unroll
                for (int j = 0; j < TSP; j++)
                    cpa4(u_fk + (p * TSP + j) * FD * 4,
                         g_fktab + s_q[s * TSP + j] * FD + tid);
            }
            CPA_COMMIT();
        }

        // ---- Phase A x4 ----------------------------------------------------
        const float* sep = s_e + p * TSP * VM;
        const float* sap = s_a + p * TSP * VM;
        const float* swp = s_w + p * TSP * MSZ;
        #pragma unroll
        for (int j = 0; j < TSP; j++) {
            const float e_c = sep[j * VM + tid];
            const float a_c = sap[j * VM + tid];
            const ull ne2 = pk2(-e_c, -e_c);
            const ull a2  = pk2(a_c, a_c);
            ull r0 = 0ull, r1 = 0ull, r2 = 0ull, r3 = 0ull;
            const ulonglong2* sw2 =
                reinterpret_cast<const ulonglong2*>(swp + j * MSZ);
            #pragma unroll
            for (int m4 = 0; m4 < 16; m4++) {
                const ulonglong2 wp = sw2[m4];
                const ull mA = mv2[2 * m4], mB = mv2[2 * m4 + 1];
                if (m4 & 1) { r2 = fma2(wp.x, mA, r2); r3 = fma2(wp.y, mB, r3); }
                else        { r0 = fma2(wp.x, mA, r0); r1 = fma2(wp.y, mB, r1); }
                const ull tA = fma2(ne2, mA, a2);
                const ull tB = fma2(ne2, mB, a2);
                mv2[2 * m4]     = fma2(wp.x, tA, mA);
                mv2[2 * m4 + 1] = fma2(wp.y, tB, mB);
            }
            float x0, x1, x2, x3, x4, x5, x6, x7;
            upk2(r0, x0, x1); upk2(r1, x2, x3);
            upk2(r2, x4, x5); upk2(r3, x6, x7);
            s_r[j * VM + tid] = ((x0 + x1) + (x2 + x3)) + ((x4 + x5) + (x6 + x7));
        }

        // ---- Phase E for span s-1 (fk in parity pn buffer) -----------------
        if (s > 0 && tid < FD) {
            const float* fkq = s_fk + pn * TSP * FD;
            #pragma unroll
            for (int j = 0; j < TSP; j++) {
                const float pre = s_fp[j * VM + f] + s_fp[j * VM + 128 + f]
                                + fkq[j * FD + f];
                float term = wp_f * tanhf(pre);
                #pragma unroll
                for (int o = 16; o > 0; o >>= 1)
                    term += __shfl_xor_sync(0xffffffffu, term, o);
                if ((tid & 31) == 0) s_red[j * 4 + (tid >> 5)] = term;
            }
        }
        __syncthreads();                       // s_r + s_red ready

        // ---- out-store for span s-1 ---------------------------------------
        if (s > 0 && tid < TSP) {
            out[b * SS + (s - 1) * TSP + tid] = bp0
                + s_red[tid * 4 + 0] + s_red[tid * 4 + 1]
                + s_red[tid * 4 + 2] + s_red[tid * 4 + 3];
        }

        // ---- Phase B x4 ----------------------------------------------------
        #pragma unroll
        for (int j = 0; j < TSP; j++) {
            ull acc0 = 0ull, acc1 = 0ull;
            const ulonglong2* sr2 =
                reinterpret_cast<const ulonglong2*>(s_r + j * VM + h * 128);
            #pragma unroll
            for (int j4 = 0; j4 < 32; j4++) {
                const ulonglong2 rp = sr2[j4];
                acc0 = fma2(wfr[2 * j4],     rp.x, acc0);
                acc1 = fma2(wfr[2 * j4 + 1], rp.y, acc1);
            }
            float y0, y1, y2, y3;
            upk2(acc0, y0, y1); upk2(acc1, y2, y3);
            s_fp[j * VM + h * 128 + f] = (y0 + y1) + (y2 + y3);
        }

        CPA_WAIT0();
        __syncthreads();                       // span boundary: prefetches visible
    }

    // ---- epilogue: E + store for last span --------------------------------
    {
        const int pL = (NSP - 1) & 1;
        if (tid < FD) {
            const float* fkq = s_fk + pL * TSP * FD;
            #pragma unroll
            for (int j = 0; j < TSP; j++) {
                const float pre = s_fp[j * VM + f] + s_fp[j * VM + 128 + f]
                                + fkq[j * FD + f];
                float term = wp_f * tanhf(pre);
                #pragma unroll
                for (int o = 16; o > 0; o >>= 1)
                    term += __shfl_xor_sync(0xffffffffu, term, o);
                if ((tid & 31) == 0) s_red[j * 4 + (tid >> 5)] = term;
            }
        }
        __syncthreads();
        if (tid < TSP) {
            out[b * SS + (NSP - 1) * TSP + tid] = bp0
                + s_red[tid * 4 + 0] + s_red[tid * 4 + 1]
                + s_red[tid * 4 + 2] + s_red[tid * 4 + 3];
        }
    }
}

// ---------------------------------------------------------------------------
// Launch. Inputs: q, qa, k_emb, v_emb, Wf, bf, Wp, bp, We, be, Wa, ba, Mk, Mv0
// ---------------------------------------------------------------------------
extern "C" void kernel_launch(void* const* d_in, const int* in_sizes, int n_in,
                              void* d_out, int out_size)
{
    const int*   q     = (const int*)  d_in[0];
    const int*   qa    = (const int*)  d_in[1];
    const float* k_emb = (const float*)d_in[2];
    const float* v_emb = (const float*)d_in[3];
    const float* Wf    = (const float*)d_in[4];
    const float* bf    = (const float*)d_in[5];
    const float* Wp    = (const float*)d_in[6];
    const float* bp    = (const float*)d_in[7];
    const float* We    = (const float*)d_in[8];
    const float* be    = (const float*)d_in[9];
    const float* Wa    = (const float*)d_in[10];
    const float* ba    = (const float*)d_in[11];
    const float* Mk    = (const float*)d_in[12];
    const float* Mv0   = (const float*)d_in[13];
    float* out = (float*)d_out;

    cudaFuncSetAttribute(build_wfk_kernel,
                         cudaFuncAttributeMaxDynamicSharedMemorySize, WFK_SMEM);
    cudaFuncSetAttribute(dkvmn_main_kernel,
                         cudaFuncAttributeMaxDynamicSharedMemorySize, MAIN_SMEM);

    transpose_we_wa<<<dim3(8, 8, 2), dim3(32, 8)>>>(We, Wa);
    build_wfk_kernel<<<(NQ1 + WTI - 1) / WTI, 256, WFK_SMEM>>>(k_emb, Mk, Wf, bf);
    build_ea_kernel<<<(NQA1 + TI - 1) / TI, 256>>>(v_emb, be, ba);
    dkvmn_main_kernel<<<BB, 256, MAIN_SMEM>>>(q, qa, Wf, Wp, bp, Mv0, out);
}